// round 4
// baseline (speedup 1.0000x reference)
#include <cuda_runtime.h>
#include <cuda_fp16.h>
#include <cuda_bf16.h>
#include <cstdint>
#include <cstddef>

// ---------------------------------------------------------------------------
// QuantizedAttention  (B=4, S=2048, H=1024)
//   quantize() in the reference == IEEE fp16 round-to-nearest-even (e5m10,
//   exponent clamp == subnormal handling, clip == satfinite). So the whole
//   pipeline is an fp16 dataflow; __float2half_rn is bit-exact vs reference.
//   QKV projection needs f32-ish input precision -> 2-term bf16 split
//   (hh + hl + lh) folded into one GEMM with K_eff = 3*1024.
// ---------------------------------------------------------------------------

namespace {
constexpr int Bn = 4;
constexpr int Sn = 2048;
constexpr int Hn = 1024;
constexpr int Mn = Bn * Sn;          // 8192

constexpr int BM = 128, BN = 128, BK = 32;
}

// ---- scratch (device globals; allocation is forbidden) --------------------
__device__ __align__(16) uint16_t g_xhi[Mn * Hn];          // bf16
__device__ __align__(16) uint16_t g_xlo[Mn * Hn];          // bf16
__device__ __align__(16) uint16_t g_whi[3 * Hn * Hn];      // bf16: [Wq|Wk|Wv]
__device__ __align__(16) uint16_t g_wlo[3 * Hn * Hn];      // bf16
__device__ __align__(16) uint16_t g_q[Mn * Hn];            // fp16 [B,S,H]
__device__ __align__(16) uint16_t g_k[Mn * Hn];            // fp16 [B,S,H]
__device__ __align__(16) uint16_t g_vt[Bn * Hn * Sn];      // fp16 [B,H,S] (V^T)
__device__ __align__(16) uint16_t g_s[Bn * Sn * Sn];       // fp16 scores/probs

// ---- small PTX helpers ----------------------------------------------------
__device__ __forceinline__ uint32_t smem_u32(const void* p) {
    return (uint32_t)__cvta_generic_to_shared(p);
}
__device__ __forceinline__ void cp16(uint32_t s, const void* g) {
    asm volatile("cp.async.cg.shared.global [%0], [%1], 16;\n" :: "r"(s), "l"(g));
}
__device__ __forceinline__ void cp_commit() {
    asm volatile("cp.async.commit_group;\n" ::: "memory");
}
template <int N>
__device__ __forceinline__ void cp_wait() {
    asm volatile("cp.async.wait_group %0;\n" :: "n"(N) : "memory");
}
__device__ __forceinline__ void ldm_x4(uint32_t* r, uint32_t addr) {
    asm volatile("ldmatrix.sync.aligned.m8n8.x4.shared.b16 {%0,%1,%2,%3}, [%4];\n"
                 : "=r"(r[0]), "=r"(r[1]), "=r"(r[2]), "=r"(r[3]) : "r"(addr));
}
template <bool BF16>
__device__ __forceinline__ void mma_16816(float* d, const uint32_t* a, const uint32_t* b) {
    if constexpr (BF16) {
        asm volatile(
            "mma.sync.aligned.m16n8k16.row.col.f32.bf16.bf16.f32 "
            "{%0,%1,%2,%3},{%4,%5,%6,%7},{%8,%9},{%0,%1,%2,%3};\n"
            : "+f"(d[0]), "+f"(d[1]), "+f"(d[2]), "+f"(d[3])
            : "r"(a[0]), "r"(a[1]), "r"(a[2]), "r"(a[3]), "r"(b[0]), "r"(b[1]));
    } else {
        asm volatile(
            "mma.sync.aligned.m16n8k16.row.col.f32.f16.f16.f32 "
            "{%0,%1,%2,%3},{%4,%5,%6,%7},{%8,%9},{%0,%1,%2,%3};\n"
            : "+f"(d[0]), "+f"(d[1]), "+f"(d[2]), "+f"(d[3])
            : "r"(a[0]), "r"(a[1]), "r"(a[2]), "r"(a[3]), "r"(b[0]), "r"(b[1]));
    }
}

// XOR swizzle on 16B chunks within a 64B row: conflict-free for both the
// cp.async stores and every ldmatrix 8-row read group.
__device__ __forceinline__ uint32_t swz(int row, int colElem) {
    int chunk = (colElem >> 3) ^ ((row >> 1) & 3);
    return (uint32_t)((chunk << 3) | (colElem & 7));
}

// ---- split f32 -> bf16 hi/lo ----------------------------------------------
__global__ void k_split(const float* __restrict__ src, int which, int n) {
    int i = blockIdx.x * 256 + threadIdx.x;
    if (i >= n) return;
    uint16_t* hi;
    uint16_t* lo;
    if (which == 0) { hi = g_xhi; lo = g_xlo; }
    else {
        int off = (which - 1) * Hn * Hn;
        hi = g_whi + off; lo = g_wlo + off;
    }
    float v = src[i];
    __nv_bfloat16 h = __float2bfloat16(v);
    float hf = __bfloat162float(h);
    __nv_bfloat16 l = __float2bfloat16(v - hf);
    hi[i] = __bfloat16_as_ushort(h);
    lo[i] = __bfloat16_as_ushort(l);
}

// ---- generic 128x128x32 double-buffered tensor-core GEMM ------------------
// MODE 0: QKV  (bf16, K_eff = 3*1024: hh + hl + lh split terms)
//   A = x[M,1024] row-major; B = W[o,h] (k-contig); epi: +bias, fp16-RN;
//   Q/K stored [B,S,H]; V stored transposed [B,H,S].
// MODE 1: scores (fp16) per batch: Q x K^T * (1/32), fp16-RN -> g_s
// MODE 2: out    (fp16) per batch: attn x V^T -> f32 d_out
template <int MODE>
__global__ __launch_bounds__(256, 2) void gemm_k(
    const float* __restrict__ bq, const float* __restrict__ bk,
    const float* __restrict__ bv, float* __restrict__ outF) {

    constexpr bool BF = (MODE == 0);
    constexpr int KT = (MODE == 0) ? 96 : ((MODE == 1) ? 32 : 64);

    __shared__ uint16_t As[2][BM][BK];   // 16 KB
    __shared__ uint16_t Bs[2][BM][BK];   // 16 KB

    const int tid  = threadIdx.x;
    const int warp = tid >> 5;
    const int lane = tid & 31;
    const int wm = warp >> 2;             // 0..1 (64-row warp tiles)
    const int wn = warp & 3;              // 0..3 (32-col warp tiles)
    const int m0 = blockIdx.y * BM;
    const int n0 = blockIdx.x * BN;
    const int bz = blockIdx.z;

    const uint32_t asBase = smem_u32(&As[0][0][0]);
    const uint32_t bsBase = smem_u32(&Bs[0][0][0]);

    auto load_tile = [&](int kb, int buf) {
        const uint16_t* ap;
        const uint16_t* bp;
        int kin, lda, ldb;
        if constexpr (MODE == 0) {
            int seg = kb >> 5;            // 0:hh 1:hl 2:lh
            kin = (kb & 31) * BK;
            ap = (seg < 2) ? g_xhi : g_xlo;
            bp = (seg == 1) ? g_wlo : g_whi;
            lda = Hn; ldb = Hn;
        } else if constexpr (MODE == 1) {
            kin = kb * BK;
            ap = g_q + (size_t)bz * Sn * Hn;
            bp = g_k + (size_t)bz * Sn * Hn;
            lda = Hn; ldb = Hn;
        } else {
            kin = kb * BK;
            ap = g_s + (size_t)bz * Sn * Sn;
            bp = g_vt + (size_t)bz * Hn * Sn;
            lda = Sn; ldb = Sn;
        }
        // 128 rows x 4 chunks of 16B per tile; 512 cp.async per tile per matrix
#pragma unroll
        for (int i = 0; i < 2; i++) {
            int c = tid + i * 256;
            int row = c >> 2, cc = (c & 3) * 8;
            cp16(asBase + (uint32_t)((buf * BM + row) * BK + swz(row, cc)) * 2,
                 ap + (size_t)(m0 + row) * lda + kin + cc);
        }
#pragma unroll
        for (int i = 0; i < 2; i++) {
            int c = tid + i * 256;
            int row = c >> 2, cc = (c & 3) * 8;
            cp16(bsBase + (uint32_t)((buf * BM + row) * BK + swz(row, cc)) * 2,
                 bp + (size_t)(n0 + row) * ldb + kin + cc);
        }
    };

    float acc[4][4][4];
#pragma unroll
    for (int a = 0; a < 4; a++)
#pragma unroll
        for (int b2 = 0; b2 < 4; b2++)
#pragma unroll
            for (int e = 0; e < 4; e++) acc[a][b2][e] = 0.f;

    load_tile(0, 0);
    cp_commit();

    for (int kb = 0; kb < KT; ++kb) {
        const int cur = kb & 1;
        if (kb + 1 < KT) {
            load_tile(kb + 1, cur ^ 1);
            cp_commit();
            cp_wait<1>();
        } else {
            cp_wait<0>();
        }
        __syncthreads();

#pragma unroll
        for (int s = 0; s < 2; s++) {
            const int koff = s * 16;
            uint32_t afr[4][4], bfr[2][4];
#pragma unroll
            for (int mi = 0; mi < 4; mi++) {
                int row = wm * 64 + mi * 16 + (lane & 15);
                int col = koff + ((lane >> 4) << 3);
                ldm_x4(afr[mi],
                       asBase + (uint32_t)((cur * BM + row) * BK + swz(row, col)) * 2);
            }
#pragma unroll
            for (int nj = 0; nj < 2; nj++) {
                int nrow = wn * 32 + nj * 16 + ((lane & 7) + ((lane >> 4) << 3));
                int col  = koff + (((lane >> 3) & 1) << 3);
                ldm_x4(bfr[nj],
                       bsBase + (uint32_t)((cur * BM + nrow) * BK + swz(nrow, col)) * 2);
            }
#pragma unroll
            for (int mi = 0; mi < 4; mi++)
#pragma unroll
                for (int ni = 0; ni < 4; ni++) {
                    const uint32_t* bb = &bfr[ni >> 1][(ni & 1) * 2];
                    mma_16816<BF>(acc[mi][ni], afr[mi], bb);
                }
        }
        __syncthreads();
    }

    // ---- epilogue ----
#pragma unroll
    for (int mi = 0; mi < 4; mi++)
#pragma unroll
        for (int ni = 0; ni < 4; ni++)
#pragma unroll
            for (int e = 0; e < 4; e++) {
                const int r  = m0 + wm * 64 + mi * 16 + (lane >> 2) + ((e >> 1) << 3);
                const int cg = n0 + wn * 32 + ni * 8 + ((lane & 3) << 1) + (e & 1);
                float y = acc[mi][ni][e];
                if constexpr (MODE == 0) {
                    const int w = cg >> 10;
                    const int o = cg & (Hn - 1);
                    const float* bias = (w == 0) ? bq : ((w == 1) ? bk : bv);
                    const uint16_t h = __half_as_ushort(__float2half_rn(y + bias[o]));
                    if (w == 0)       g_q[(size_t)r * Hn + o] = h;
                    else if (w == 1)  g_k[(size_t)r * Hn + o] = h;
                    else {
                        const int bb2 = r >> 11;
                        const int ss  = r & (Sn - 1);
                        g_vt[((size_t)bb2 * Hn + o) * Sn + ss] = h;
                    }
                } else if constexpr (MODE == 1) {
                    g_s[(size_t)bz * Sn * Sn + (size_t)r * Sn + cg] =
                        __half_as_ushort(__float2half_rn(y * 0.03125f));
                } else {
                    outF[((size_t)bz * Sn + (size_t)r) * Hn + cg] = y;
                }
            }
}

// ---- row softmax over 2048 fp16 scores, fp16-RN result in-place -----------
__global__ void k_softmax(void) {
    const int row = blockIdx.x;                       // 0..8191
    const int tid = threadIdx.x;                      // 256 threads
    uint32_t* p32 = reinterpret_cast<uint32_t*>(g_s + (size_t)row * Sn);

    float v[8];
    float mx = -3.4e38f;
#pragma unroll
    for (int i = 0; i < 4; i++) {
        uint32_t u = p32[tid + i * 256];
        float a = __half2float(__ushort_as_half((unsigned short)(u & 0xFFFFu)));
        float b = __half2float(__ushort_as_half((unsigned short)(u >> 16)));
        v[2 * i] = a; v[2 * i + 1] = b;
        mx = fmaxf(mx, fmaxf(a, b));
    }
    __shared__ float red[256];
    red[tid] = mx; __syncthreads();
#pragma unroll
    for (int s = 128; s > 0; s >>= 1) {
        if (tid < s) red[tid] = fmaxf(red[tid], red[tid + s]);
        __syncthreads();
    }
    mx = red[0];
    __syncthreads();

    float sum = 0.f;
#pragma unroll
    for (int i = 0; i < 8; i++) { v[i] = expf(v[i] - mx); sum += v[i]; }
    red[tid] = sum; __syncthreads();
#pragma unroll
    for (int s = 128; s > 0; s >>= 1) {
        if (tid < s) red[tid] += red[tid + s];
        __syncthreads();
    }
    sum = red[0];

#pragma unroll
    for (int i = 0; i < 4; i++) {
        uint32_t lo = (uint32_t)__half_as_ushort(__float2half_rn(v[2 * i] / sum));
        uint32_t hi = (uint32_t)__half_as_ushort(__float2half_rn(v[2 * i + 1] / sum));
        p32[tid + i * 256] = lo | (hi << 16);
    }
}

// ---------------------------------------------------------------------------
extern "C" void kernel_launch(void* const* d_in, const int* in_sizes, int n_in,
                              void* d_out, int out_size) {
    (void)in_sizes; (void)n_in; (void)out_size;
    const float* x  = (const float*)d_in[0];
    const float* Wq = (const float*)d_in[1];
    const float* bq = (const float*)d_in[2];
    const float* Wk = (const float*)d_in[3];
    const float* bk = (const float*)d_in[4];
    const float* Wv = (const float*)d_in[5];
    const float* bv = (const float*)d_in[6];
    float* out = (float*)d_out;

    // 1) bf16 hi/lo splits of x and weights
    k_split<<<(Mn * Hn + 255) / 256, 256>>>(x,  0, Mn * Hn);
    k_split<<<(Hn * Hn + 255) / 256, 256>>>(Wq, 1, Hn * Hn);
    k_split<<<(Hn * Hn + 255) / 256, 256>>>(Wk, 2, Hn * Hn);
    k_split<<<(Hn * Hn + 255) / 256, 256>>>(Wv, 3, Hn * Hn);

    // 2) fused QKV projection (split GEMM, K_eff = 3072) + bias + fp16 quantize
    gemm_k<0><<<dim3(3 * Hn / BN, Mn / BM, 1), 256>>>(bq, bk, bv, nullptr);

    // 3) scores = Q K^T / 32, fp16 quantize
    gemm_k<1><<<dim3(Sn / BN, Sn / BM, Bn), 256>>>(nullptr, nullptr, nullptr, nullptr);

    // 4) softmax rows, fp16 quantize (in-place)
    k_softmax<<<Mn, 256>>>();

    // 5) out = attn @ V  (f32)
    gemm_k<2><<<dim3(Hn / BN, Sn / BM, Bn), 256>>>(nullptr, nullptr, nullptr, out);
}

// round 7
// speedup vs baseline: 1.1166x; 1.1166x over previous
#include <cuda_runtime.h>
#include <cuda_fp16.h>
#include <cuda_bf16.h>
#include <cstdint>
#include <cstddef>

// ---------------------------------------------------------------------------
// QuantizedAttention (B=4, S=2048, H=1024)
//   quantize() == IEEE fp16 RN-even (e5m10 + clamp == subnormals, clip ==
//   satfinite). Whole pipeline is an fp16 dataflow; __float2half_rn is
//   bit-exact vs the reference. QKV projection uses a bf16 hi/lo split GEMM
//   (hh+hl+lh folded into one K_eff=3072 GEMM) for exact fp16 rounding.
//   NOTE: harness builds with virtual arch compute_103 (no 'a') -> tcgen05 is
//   unavailable; legacy mma.sync is the tensor path. This revision: BK=64,
//   3-stage cp.async, ONE __syncthreads per k-step (was 2 per 32-K step).
// ---------------------------------------------------------------------------

namespace {
constexpr int Bn = 4, Sn = 2048, Hn = 1024, Mn = Bn * Sn;

constexpr int BM = 128, BN = 128, BK = 64;
constexpr int NS = 3;                                   // pipeline stages
constexpr int MAT_BYTES   = BM * BK * 2;                // 16 KB (A or B)
constexpr int STAGE_BYTES = 2 * MAT_BYTES;              // 32 KB
constexpr int SMEM_TOTAL  = NS * STAGE_BYTES;           // 96 KB dynamic
}

// ---- scratch (device globals; allocation forbidden) -----------------------
__device__ __align__(16) uint16_t g_xhi[Mn * Hn];
__device__ __align__(16) uint16_t g_xlo[Mn * Hn];
__device__ __align__(16) uint16_t g_whi[3 * Hn * Hn];
__device__ __align__(16) uint16_t g_wlo[3 * Hn * Hn];
__device__ __align__(16) uint16_t g_q[Mn * Hn];        // fp16 [B,S,H]
__device__ __align__(16) uint16_t g_k[Mn * Hn];        // fp16 [B,S,H]
__device__ __align__(16) uint16_t g_vt[Bn * Hn * Sn];  // fp16 [B,H,S]
__device__ __align__(16) uint16_t g_s[Bn * Sn * Sn];   // fp16 scores/probs

// ---- PTX helpers ----------------------------------------------------------
__device__ __forceinline__ uint32_t smem_u32(const void* p) {
    return (uint32_t)__cvta_generic_to_shared(p);
}
__device__ __forceinline__ void cp16(uint32_t s, const void* g) {
    asm volatile("cp.async.cg.shared.global [%0], [%1], 16;\n" :: "r"(s), "l"(g));
}
__device__ __forceinline__ void cp_commit() {
    asm volatile("cp.async.commit_group;\n" ::: "memory");
}
template <int N>
__device__ __forceinline__ void cp_wait() {
    asm volatile("cp.async.wait_group %0;\n" :: "n"(N) : "memory");
}
__device__ __forceinline__ void ldm_x4(uint32_t* r, uint32_t addr) {
    asm volatile("ldmatrix.sync.aligned.m8n8.x4.shared.b16 {%0,%1,%2,%3}, [%4];\n"
                 : "=r"(r[0]), "=r"(r[1]), "=r"(r[2]), "=r"(r[3]) : "r"(addr));
}
template <bool BF16>
__device__ __forceinline__ void mma_16816(float* d, const uint32_t* a, const uint32_t* b) {
    if constexpr (BF16) {
        asm volatile(
            "mma.sync.aligned.m16n8k16.row.col.f32.bf16.bf16.f32 "
            "{%0,%1,%2,%3},{%4,%5,%6,%7},{%8,%9},{%0,%1,%2,%3};\n"
            : "+f"(d[0]), "+f"(d[1]), "+f"(d[2]), "+f"(d[3])
            : "r"(a[0]), "r"(a[1]), "r"(a[2]), "r"(a[3]), "r"(b[0]), "r"(b[1]));
    } else {
        asm volatile(
            "mma.sync.aligned.m16n8k16.row.col.f32.f16.f16.f32 "
            "{%0,%1,%2,%3},{%4,%5,%6,%7},{%8,%9},{%0,%1,%2,%3};\n"
            : "+f"(d[0]), "+f"(d[1]), "+f"(d[2]), "+f"(d[3])
            : "r"(a[0]), "r"(a[1]), "r"(a[2]), "r"(a[3]), "r"(b[0]), "r"(b[1]));
    }
}

// ---- split f32 -> bf16 hi/lo ----------------------------------------------
__global__ void k_split(const float* __restrict__ src, int which, int n) {
    int i = blockIdx.x * 256 + threadIdx.x;
    if (i >= n) return;
    uint16_t* hi;
    uint16_t* lo;
    if (which == 0) { hi = g_xhi; lo = g_xlo; }
    else {
        int off = (which - 1) * Hn * Hn;
        hi = g_whi + off; lo = g_wlo + off;
    }
    float v = src[i];
    __nv_bfloat16 h = __float2bfloat16(v);
    __nv_bfloat16 l = __float2bfloat16(v - __bfloat162float(h));
    hi[i] = __bfloat16_as_ushort(h);
    lo[i] = __bfloat16_as_ushort(l);
}

// ---- 128x128x64, 3-stage cp.async, legacy mma.sync tensor GEMM ------------
// MODE 0: QKV  (bf16 split, K_eff=3072: hh|hl|lh segments of 1024)
// MODE 1: scores = Q K^T * (1/32) -> fp16 g_s   (per batch)
// MODE 2: out    = attn @ V^T -> f32 d_out      (per batch)
template <int MODE>
__global__ __launch_bounds__(256, 2) void gemm_k(
    const float* __restrict__ bq, const float* __restrict__ bk,
    const float* __restrict__ bv, float* __restrict__ outF) {

    constexpr bool BF = (MODE == 0);
    constexpr int KT = (MODE == 0) ? 48 : ((MODE == 1) ? 16 : 32);  // K / 64

    extern __shared__ __align__(128) uint16_t sh[];   // [NS][2][128][64]

    const int tid  = threadIdx.x;
    const int warp = tid >> 5;
    const int lane = tid & 31;
    const int wm = warp >> 2;             // 0..1 (64-row warp tiles)
    const int wn = warp & 3;              // 0..3 (32-col warp tiles)
    const int m0 = blockIdx.y * BM;
    const int n0 = blockIdx.x * BN;
    const int bz = blockIdx.z;

    const uint32_t shBase = smem_u32(sh);

    // cp.async fill of one stage: A tile then B tile, 128B rows, XOR swizzle
    auto load_stage = [&](int j) {
        const uint32_t sbase = shBase + (uint32_t)(j % NS) * STAGE_BYTES;
        const uint16_t* ap;
        const uint16_t* bp;
        int kin, lda, ldb;
        if constexpr (MODE == 0) {
            int seg = j >> 4;             // 0:hh 1:hl 2:lh (16 iters each)
            kin = (j & 15) * BK;
            ap = (seg < 2) ? g_xhi : g_xlo;
            bp = (seg == 1) ? g_wlo : g_whi;
            lda = Hn; ldb = Hn;
        } else if constexpr (MODE == 1) {
            kin = j * BK;
            ap = g_q + (size_t)bz * Sn * Hn;
            bp = g_k + (size_t)bz * Sn * Hn;
            lda = Hn; ldb = Hn;
        } else {
            kin = j * BK;
            ap = g_s + (size_t)bz * Sn * Sn;
            bp = g_vt + (size_t)bz * Hn * Sn;
            lda = Sn; ldb = Sn;
        }
        // 128 rows x 8 chunks(16B) per matrix = 1024 chunks; 4 per thread
#pragma unroll
        for (int it = 0; it < 4; it++) {
            int i = tid + it * 256;
            int row = i >> 3, c = i & 7;
            uint32_t dst = sbase + (uint32_t)(row * 128 + ((c ^ (row & 7)) << 4));
            cp16(dst, ap + (size_t)(m0 + row) * lda + kin + c * 8);
        }
#pragma unroll
        for (int it = 0; it < 4; it++) {
            int i = tid + it * 256;
            int row = i >> 3, c = i & 7;
            uint32_t dst = sbase + (uint32_t)MAT_BYTES +
                           (uint32_t)(row * 128 + ((c ^ (row & 7)) << 4));
            cp16(dst, bp + (size_t)(n0 + row) * ldb + kin + c * 8);
        }
    };

    float acc[4][4][4];
#pragma unroll
    for (int a = 0; a < 4; a++)
#pragma unroll
        for (int b2 = 0; b2 < 4; b2++)
#pragma unroll
            for (int e = 0; e < 4; e++) acc[a][b2][e] = 0.f;

    // prologue: stages 0,1 in flight
    load_stage(0); cp_commit();
    load_stage(1); cp_commit();

    for (int j = 0; j < KT; ++j) {
        cp_wait<1>();          // stage j resident
        __syncthreads();       // all warps past compute j-1 (stage reuse safe)
        if (j + 2 < KT) load_stage(j + 2);
        cp_commit();

        const uint32_t aS = shBase + (uint32_t)(j % NS) * STAGE_BYTES;
        const uint32_t bS = aS + MAT_BYTES;

#pragma unroll
        for (int kc = 0; kc < 4; kc++) {            // 4 chunks of k16
            const int lc = kc * 2;                  // logical 16B chunk pair base
            uint32_t afr[4][4], bfr[2][4];
#pragma unroll
            for (int mi = 0; mi < 4; mi++) {
                int row = wm * 64 + mi * 16 + (lane & 15);
                int ch  = (lc + (lane >> 4)) ^ (row & 7);
                ldm_x4(afr[mi], aS + (uint32_t)(row * 128 + (ch << 4)));
            }
#pragma unroll
            for (int nj = 0; nj < 2; nj++) {
                int nrow = wn * 32 + nj * 16 + ((lane & 7) + ((lane >> 4) << 3));
                int ch   = (lc + ((lane >> 3) & 1)) ^ (nrow & 7);
                ldm_x4(bfr[nj], bS + (uint32_t)(nrow * 128 + (ch << 4)));
            }
#pragma unroll
            for (int mi = 0; mi < 4; mi++)
#pragma unroll
                for (int ni = 0; ni < 4; ni++)
                    mma_16816<BF>(acc[mi][ni], afr[mi], &bfr[ni >> 1][(ni & 1) * 2]);
        }
    }

    // ---- epilogue ----
#pragma unroll
    for (int mi = 0; mi < 4; mi++)
#pragma unroll
        for (int ni = 0; ni < 4; ni++)
#pragma unroll
            for (int e = 0; e < 4; e++) {
                const int r  = m0 + wm * 64 + mi * 16 + (lane >> 2) + ((e >> 1) << 3);
                const int cg = n0 + wn * 32 + ni * 8 + ((lane & 3) << 1) + (e & 1);
                float y = acc[mi][ni][e];
                if constexpr (MODE == 0) {
                    const int w = cg >> 10;
                    const int o = cg & (Hn - 1);
                    const float* bias = (w == 0) ? bq : ((w == 1) ? bk : bv);
                    const uint16_t h = __half_as_ushort(__float2half_rn(y + bias[o]));
                    if (w == 0)       g_q[(size_t)r * Hn + o] = h;
                    else if (w == 1)  g_k[(size_t)r * Hn + o] = h;
                    else {
                        const int bb2 = r >> 11;
                        const int ss  = r & (Sn - 1);
                        g_vt[((size_t)bb2 * Hn + o) * Sn + ss] = h;
                    }
                } else if constexpr (MODE == 1) {
                    g_s[(size_t)bz * Sn * Sn + (size_t)r * Sn + cg] =
                        __half_as_ushort(__float2half_rn(y * 0.03125f));
                } else {
                    outF[((size_t)bz * Sn + (size_t)r) * Hn + cg] = y;
                }
            }
}

// ---- row softmax over 2048 fp16 scores, fp16-RN in-place ------------------
__global__ void k_softmax(void) {
    const int row = blockIdx.x;
    const int tid = threadIdx.x;
    uint32_t* p32 = reinterpret_cast<uint32_t*>(g_s + (size_t)row * Sn);

    float v[8];
    float mx = -3.4e38f;
#pragma unroll
    for (int i = 0; i < 4; i++) {
        uint32_t u = p32[tid + i * 256];
        float a = __half2float(__ushort_as_half((unsigned short)(u & 0xFFFFu)));
        float b = __half2float(__ushort_as_half((unsigned short)(u >> 16)));
        v[2 * i] = a; v[2 * i + 1] = b;
        mx = fmaxf(mx, fmaxf(a, b));
    }
    __shared__ float red[256];
    red[tid] = mx; __syncthreads();
#pragma unroll
    for (int s = 128; s > 0; s >>= 1) {
        if (tid < s) red[tid] = fmaxf(red[tid], red[tid + s]);
        __syncthreads();
    }
    mx = red[0];
    __syncthreads();

    float sum = 0.f;
#pragma unroll
    for (int i = 0; i < 8; i++) { v[i] = expf(v[i] - mx); sum += v[i]; }
    red[tid] = sum; __syncthreads();
#pragma unroll
    for (int s = 128; s > 0; s >>= 1) {
        if (tid < s) red[tid] += red[tid + s];
        __syncthreads();
    }
    sum = red[0];

#pragma unroll
    for (int i = 0; i < 4; i++) {
        uint32_t lo = (uint32_t)__half_as_ushort(__float2half_rn(v[2 * i] / sum));
        uint32_t hi = (uint32_t)__half_as_ushort(__float2half_rn(v[2 * i + 1] / sum));
        p32[tid + i * 256] = lo | (hi << 16);
    }
}

// ---------------------------------------------------------------------------
extern "C" void kernel_launch(void* const* d_in, const int* in_sizes, int n_in,
                              void* d_out, int out_size) {
    (void)in_sizes; (void)n_in; (void)out_size;
    const float* x  = (const float*)d_in[0];
    const float* Wq = (const float*)d_in[1];
    const float* bq = (const float*)d_in[2];
    const float* Wk = (const float*)d_in[3];
    const float* bk = (const float*)d_in[4];
    const float* Wv = (const float*)d_in[5];
    const float* bv = (const float*)d_in[6];
    float* out = (float*)d_out;

    // opt-in >48KB dynamic smem (idempotent; not a stream op, capture-safe)
    cudaFuncSetAttribute(gemm_k<0>, cudaFuncAttributeMaxDynamicSharedMemorySize, SMEM_TOTAL);
    cudaFuncSetAttribute(gemm_k<1>, cudaFuncAttributeMaxDynamicSharedMemorySize, SMEM_TOTAL);
    cudaFuncSetAttribute(gemm_k<2>, cudaFuncAttributeMaxDynamicSharedMemorySize, SMEM_TOTAL);

    // 1) bf16 hi/lo splits
    k_split<<<(Mn * Hn + 255) / 256, 256>>>(x,  0, Mn * Hn);
    k_split<<<(Hn * Hn + 255) / 256, 256>>>(Wq, 1, Hn * Hn);
    k_split<<<(Hn * Hn + 255) / 256, 256>>>(Wk, 2, Hn * Hn);
    k_split<<<(Hn * Hn + 255) / 256, 256>>>(Wv, 3, Hn * Hn);

    // 2) fused QKV projection (split GEMM, K_eff=3072) + bias + fp16 quantize
    gemm_k<0><<<dim3(3 * Hn / BN, Mn / BM, 1), 256, SMEM_TOTAL>>>(bq, bk, bv, nullptr);

    // 3) scores = Q K^T / 32, fp16 quantize
    gemm_k<1><<<dim3(Sn / BN, Sn / BM, Bn), 256, SMEM_TOTAL>>>(nullptr, nullptr, nullptr, nullptr);

    // 4) softmax rows, fp16 quantize (in-place)
    k_softmax<<<Mn, 256>>>();

    // 5) out = attn @ V (f32)
    gemm_k<2><<<dim3(Hn / BN, Sn / BM, Bn), 256, SMEM_TOTAL>>>(nullptr, nullptr, nullptr, out);
}